// round 3
// baseline (speedup 1.0000x reference)
#include <cuda_runtime.h>
#include <math.h>

#define BN 4
#define TT 1024
#define NTOK 4096          // B*T
#define SWc 96
#define FBc 64
#define Fc 6144            // SW*FB
#define EMBc 512
#define Hc 3
#define DHc 32
#define FFc 384

// ---------------- scratch (static device globals; no allocs) ----------------
__device__ float  g_mid[(size_t)NTOK * Fc];    // (B,T,F) intermediate
__device__ float  g_emb[(size_t)NTOK * EMBc];  // (B,T,EMB) pre-norm
__device__ double g_part[256];                 // per-block sum / sumsq partials
__device__ float  g_stats[2];                  // mu, rstd

// ---------------- kernel 1: per-token rel-attention + FFN -------------------
#define XS 97      // row stride for 96-wide tiles (conflict-free)
#define SSx 65     // score row stride
#define ES 33      // Er row stride
#define HS 385     // hidden row stride

#define OFF_ATT 0          // 64*97 = 6208   (xs -> att_out -> staged output)
#define OFF_Q   6208       // 64*97
#define OFF_K   12416
#define OFF_V   18624      // ends 24832
#define OFF_HID 6208       // 64*385 = 24640, overlays Q/K/V (dead by FFN), ends 30848
#define OFF_W   30848      // 12288 floats: W stage / er+S+R / FFN weight tiles
#define SMEM_FLOATS 43136  // 172544 bytes

__global__ __launch_bounds__(256) void attn_ffn_kernel(
    const float* __restrict__ x,
    const float* __restrict__ Wq, const float* __restrict__ bq,
    const float* __restrict__ Wk, const float* __restrict__ bk,
    const float* __restrict__ Wv, const float* __restrict__ bv,
    const float* __restrict__ Er,
    const float* __restrict__ W1, const float* __restrict__ b1,
    const float* __restrict__ W2, const float* __restrict__ b2)
{
    extern __shared__ float sm[];
    float* s_att = sm + OFF_ATT;
    float* s_q   = sm + OFF_Q;
    float* s_k   = sm + OFF_K;
    float* s_v   = sm + OFF_V;
    float* s_hid = sm + OFF_HID;
    float* s_w   = sm + OFF_W;
    float* s_er  = s_w + 9216;   // survives QKV staging (staging uses [0,9216))
    float* s_S   = s_w;          // attention phase only (W stage dead)
    float* s_R   = s_w + 4160;

    const int tid = threadIdx.x;
    const int n   = blockIdx.x;
    const size_t base = (size_t)n * Fc;

    // xr[l][d] = x[n, d*FB + l]  (reshape(SW,FB) then transpose)
    for (int idx = tid; idx < Fc; idx += 256) {
        int d = idx >> 6, l = idx & 63;
        s_att[l * XS + d] = x[base + idx];
    }
    for (int idx = tid; idx < 64 * 32; idx += 256) {
        int j = idx >> 5, d = idx & 31;
        s_er[j * ES + d] = Er[idx];
    }
    __syncthreads();

    // ---- QKV projections: (64x96) @ (96x96) with W staged in smem ----
    const float* Wmats[3] = {Wq, Wk, Wv};
    const float* bvecs[3] = {bq, bk, bv};
    float* qkv[3] = {s_q, s_k, s_v};
    const int r0a = (tid >> 4) * 4;   // 16 row groups * 4
    const int c0a = (tid & 15) * 6;   // 16 col groups * 6
    for (int w = 0; w < 3; ++w) {
        const float* W = Wmats[w];
        for (int idx = tid; idx < 9216; idx += 256) s_w[idx] = W[idx];
        __syncthreads();
        float acc[4][6];
        #pragma unroll
        for (int r = 0; r < 4; ++r)
            #pragma unroll
            for (int c = 0; c < 6; ++c) acc[r][c] = 0.f;
        #pragma unroll 4
        for (int i = 0; i < 96; ++i) {
            float xv[4];
            #pragma unroll
            for (int r = 0; r < 4; ++r) xv[r] = s_att[(r0a + r) * XS + i];
            #pragma unroll
            for (int c = 0; c < 6; ++c) {
                float wv = s_w[i * 96 + c0a + c];
                #pragma unroll
                for (int r = 0; r < 4; ++r) acc[r][c] += xv[r] * wv;
            }
        }
        const float* bb = bvecs[w];
        float* o = qkv[w];
        #pragma unroll
        for (int r = 0; r < 4; ++r)
            #pragma unroll
            for (int c = 0; c < 6; ++c)
                o[(r0a + r) * XS + c0a + c] = acc[r][c] + bb[c0a + c];
        __syncthreads();
    }

    // ---- relative attention, per head ----
    const float scale = 0.17677669529663687f;   // 1/sqrt(32)
    const int wid = tid >> 5, lane = tid & 31;
    const int l0 = (tid >> 4) * 4, m0 = (tid & 15) * 4;
    const int oc0 = (tid & 15) * 2;
    for (int h = 0; h < 3; ++h) {
        const int hb = h * 32;
        float aS[4][4], aR[4][4];
        #pragma unroll
        for (int r = 0; r < 4; ++r)
            #pragma unroll
            for (int c = 0; c < 4; ++c) { aS[r][c] = 0.f; aR[r][c] = 0.f; }
        #pragma unroll 4
        for (int d = 0; d < 32; ++d) {
            float qv[4], kv[4], ev[4];
            #pragma unroll
            for (int r = 0; r < 4; ++r) qv[r] = s_q[(l0 + r) * XS + hb + d];
            #pragma unroll
            for (int c = 0; c < 4; ++c) kv[c] = s_k[(m0 + c) * XS + hb + d];
            #pragma unroll
            for (int c = 0; c < 4; ++c) ev[c] = s_er[(m0 + c) * ES + d];
            #pragma unroll
            for (int r = 0; r < 4; ++r)
                #pragma unroll
                for (int c = 0; c < 4; ++c) {
                    aS[r][c] += qv[r] * kv[c];
                    aR[r][c] += qv[r] * ev[c];
                }
        }
        #pragma unroll
        for (int r = 0; r < 4; ++r)
            #pragma unroll
            for (int c = 0; c < 4; ++c) {
                s_S[(l0 + r) * SSx + m0 + c] = aS[r][c];
                s_R[(l0 + r) * SSx + m0 + c] = aR[r][c];
            }
        __syncthreads();

        // softmax: warp per row; srel[l][m] = R[l][m+63-l] for m<=l
        for (int l = wid; l < 64; l += 8) {
            int m1 = lane + 32;
            float v0 = (lane <= l)
                ? (s_S[l * SSx + lane] + s_R[l * SSx + lane + 63 - l]) * scale : -1e30f;
            float v1 = (m1 <= l)
                ? (s_S[l * SSx + m1] + s_R[l * SSx + m1 + 63 - l]) * scale : -1e30f;
            float mx = fmaxf(v0, v1);
            #pragma unroll
            for (int o = 16; o; o >>= 1) mx = fmaxf(mx, __shfl_xor_sync(0xffffffffu, mx, o));
            float e0 = __expf(v0 - mx), e1 = __expf(v1 - mx);
            float ssum = e0 + e1;
            #pragma unroll
            for (int o = 16; o; o >>= 1) ssum += __shfl_xor_sync(0xffffffffu, ssum, o);
            float inv = 1.0f / ssum;
            s_S[l * SSx + lane] = e0 * inv;
            s_S[l * SSx + m1]   = e1 * inv;
        }
        __syncthreads();

        // O = P @ V (64x32 per head) -> att_out columns [hb, hb+32)
        float ao[4][2];
        #pragma unroll
        for (int r = 0; r < 4; ++r) { ao[r][0] = 0.f; ao[r][1] = 0.f; }
        #pragma unroll 4
        for (int m = 0; m < 64; ++m) {
            float pv[4], vv[2];
            #pragma unroll
            for (int r = 0; r < 4; ++r) pv[r] = s_S[(l0 + r) * SSx + m];
            #pragma unroll
            for (int c = 0; c < 2; ++c) vv[c] = s_v[m * XS + hb + oc0 + c];
            #pragma unroll
            for (int r = 0; r < 4; ++r)
                #pragma unroll
                for (int c = 0; c < 2; ++c) ao[r][c] += pv[r] * vv[c];
        }
        #pragma unroll
        for (int r = 0; r < 4; ++r)
            #pragma unroll
            for (int c = 0; c < 2; ++c)
                s_att[(l0 + r) * XS + hb + oc0 + c] = ao[r][c];
        __syncthreads();
    }

    // ---- FFN GEMM1: hid = relu(att(64x96) @ W1(96x384) + b1) ----
    const int fr0 = (tid >> 4) * 4;
    const int fc0 = (tid & 15) * 8;
    for (int jt = 0; jt < 3; ++jt) {
        __syncthreads();
        for (int idx = tid; idx < 12288; idx += 256) {
            int i = idx >> 7, c = idx & 127;
            s_w[idx] = W1[i * FFc + jt * 128 + c];
        }
        __syncthreads();
        float acc[4][8];
        #pragma unroll
        for (int r = 0; r < 4; ++r)
            #pragma unroll
            for (int c = 0; c < 8; ++c) acc[r][c] = 0.f;
        #pragma unroll 2
        for (int i = 0; i < 96; ++i) {
            float av[4];
            #pragma unroll
            for (int r = 0; r < 4; ++r) av[r] = s_att[(fr0 + r) * XS + i];
            float4 w0 = *(const float4*)&s_w[i * 128 + fc0];
            float4 w1 = *(const float4*)&s_w[i * 128 + fc0 + 4];
            float wb[8] = {w0.x, w0.y, w0.z, w0.w, w1.x, w1.y, w1.z, w1.w};
            #pragma unroll
            for (int r = 0; r < 4; ++r)
                #pragma unroll
                for (int c = 0; c < 8; ++c) acc[r][c] += av[r] * wb[c];
        }
        #pragma unroll
        for (int r = 0; r < 4; ++r)
            #pragma unroll
            for (int c = 0; c < 8; ++c)
                s_hid[(fr0 + r) * HS + jt * 128 + fc0 + c] =
                    fmaxf(acc[r][c] + b1[jt * 128 + fc0 + c], 0.f);
    }

    // ---- FFN GEMM2: out = hid(64x384) @ W2(384x96) + b2 ----
    const int gc0 = (tid & 15) * 6;
    float acc2[4][6];
    #pragma unroll
    for (int r = 0; r < 4; ++r)
        #pragma unroll
        for (int c = 0; c < 6; ++c) acc2[r][c] = 0.f;
    for (int kt = 0; kt < 3; ++kt) {
        __syncthreads();
        for (int idx = tid; idx < 12288; idx += 256)
            s_w[idx] = W2[kt * 12288 + idx];     // [128][96] tile
        __syncthreads();
        #pragma unroll 2
        for (int i = 0; i < 128; ++i) {
            float hv[4];
            #pragma unroll
            for (int r = 0; r < 4; ++r) hv[r] = s_hid[(fr0 + r) * HS + kt * 128 + i];
            #pragma unroll
            for (int c = 0; c < 6; ++c) {
                float wv = s_w[i * 96 + gc0 + c];
                #pragma unroll
                for (int r = 0; r < 4; ++r) acc2[r][c] += hv[r] * wv;
            }
        }
    }
    __syncthreads();
    #pragma unroll
    for (int r = 0; r < 4; ++r)
        #pragma unroll
        for (int c = 0; c < 6; ++c)
            s_att[(fr0 + r) * XS + gc0 + c] = acc2[r][c] + b2[gc0 + c];
    __syncthreads();
    // emb.transpose back: mid[n, d*64 + l] = out[l][d], coalesced store
    for (int idx = tid; idx < Fc; idx += 256) {
        int d = idx >> 6, l = idx & 63;
        g_mid[base + idx] = s_att[l * XS + d];
    }
}

// ---------------- kernel 2: (4096x6144)@(6144x512)+be, + stats partials -----
#define GBM 128
#define GBN 128
#define GBK 16

__global__ __launch_bounds__(256) void we_gemm_kernel(
    const float* __restrict__ We, const float* __restrict__ be)
{
    __shared__ float As[GBK * GBM];   // As[k][m] (transposed)
    __shared__ float Bs[GBK * GBN];   // Bs[k][c]
    __shared__ double red[16];

    const int tid = threadIdx.x;
    const int e0 = blockIdx.x * GBN;
    const int n0 = blockIdx.y * GBM;
    const int r0 = (tid >> 4) * 8;
    const int c0 = (tid & 15) * 8;

    float acc[8][8];
    #pragma unroll
    for (int i = 0; i < 8; ++i)
        #pragma unroll
        for (int j = 0; j < 8; ++j) acc[i][j] = 0.f;

    for (int k0 = 0; k0 < Fc; k0 += GBK) {
        __syncthreads();
        #pragma unroll
        for (int q = 0; q < 2; ++q) {                 // A: 128x16 via float4
            int idx = tid + q * 256;
            int m = idx >> 2, kq = (idx & 3) * 4;
            float4 v = *(const float4*)&g_mid[(size_t)(n0 + m) * Fc + k0 + kq];
            As[(kq + 0) * GBM + m] = v.x;
            As[(kq + 1) * GBM + m] = v.y;
            As[(kq + 2) * GBM + m] = v.z;
            As[(kq + 3) * GBM + m] = v.w;
        }
        #pragma unroll
        for (int q = 0; q < 8; ++q) {                 // B: 16x128 coalesced
            int idx = tid + q * 256;
            int k = idx >> 7, c = idx & 127;
            Bs[idx] = We[(size_t)(k0 + k) * EMBc + e0 + c];
        }
        __syncthreads();
        #pragma unroll
        for (int k = 0; k < GBK; ++k) {
            float4 a0 = *(const float4*)&As[k * GBM + r0];
            float4 a1 = *(const float4*)&As[k * GBM + r0 + 4];
            float4 b0 = *(const float4*)&Bs[k * GBN + c0];
            float4 b1 = *(const float4*)&Bs[k * GBN + c0 + 4];
            float a[8] = {a0.x, a0.y, a0.z, a0.w, a1.x, a1.y, a1.z, a1.w};
            float b[8] = {b0.x, b0.y, b0.z, b0.w, b1.x, b1.y, b1.z, b1.w};
            #pragma unroll
            for (int i = 0; i < 8; ++i)
                #pragma unroll
                for (int j = 0; j < 8; ++j) acc[i][j] += a[i] * b[j];
        }
    }

    double s = 0.0, s2 = 0.0;
    #pragma unroll
    for (int i = 0; i < 8; ++i)
        #pragma unroll
        for (int j = 0; j < 8; ++j) {
            float v = acc[i][j] + be[e0 + c0 + j];
            g_emb[(size_t)(n0 + r0 + i) * EMBc + e0 + c0 + j] = v;
            s  += (double)v;
            s2 += (double)v * (double)v;
        }
    #pragma unroll
    for (int o = 16; o; o >>= 1) {
        s  += __shfl_xor_sync(0xffffffffu, s, o);
        s2 += __shfl_xor_sync(0xffffffffu, s2, o);
    }
    const int wid = tid >> 5, lane = tid & 31;
    if (lane == 0) { red[wid] = s; red[wid + 8] = s2; }
    __syncthreads();
    if (tid == 0) {
        double ts = 0.0, ts2 = 0.0;
        #pragma unroll
        for (int i = 0; i < 8; ++i) { ts += red[i]; ts2 += red[i + 8]; }
        int bid = blockIdx.y * gridDim.x + blockIdx.x;   // < 128, deterministic slot
        g_part[bid * 2]     = ts;
        g_part[bid * 2 + 1] = ts2;
    }
}

// ---------------- kernel 3: finalize mean / rstd ----------------------------
__global__ void stats_kernel()
{
    if (threadIdx.x == 0) {
        double s = 0.0, s2 = 0.0;
        for (int i = 0; i < 128; ++i) { s += g_part[2 * i]; s2 += g_part[2 * i + 1]; }
        double cnt = (double)NTOK * (double)EMBc;
        double mu  = s / cnt;
        double var = s2 / cnt - mu * mu;
        g_stats[0] = (float)mu;
        g_stats[1] = (float)(1.0 / sqrt(var + 1e-8));
    }
}

// ---------------- kernel 4: normalize + segment means + residual ------------
__global__ __launch_bounds__(256) void final_kernel(
    const int* __restrict__ o_enc, const float* __restrict__ r_enc,
    float* __restrict__ out)
{
    const int n = blockIdx.x;
    const int b = n >> 10, t = n & 1023;
    __shared__ int s_len;
    if (threadIdx.x == 0) {
        int len = 0;
        bool is_start = (t == 0) || (o_enc[n] != 0);
        if (is_start) {
            int tt = t + 1;
            while (tt < TT && o_enc[b * TT + tt] == 0) ++tt;
            len = tt - t;
        }
        s_len = len;
    }
    __syncthreads();
    const float mu = g_stats[0], rs = g_stats[1];
    const int len = s_len;
    for (int e = threadIdx.x; e < EMBc; e += 256) {
        size_t bi = (size_t)n * EMBc + e;
        float v = (g_emb[bi] - mu) * rs;
        float o = v + r_enc[bi];
        if (len) {
            float sum = 0.f;
            for (int s = 0; s < len; ++s)
                sum += g_emb[(size_t)(n + s) * EMBc + e];
            o += (sum / (float)len - mu) * rs;   // mean of normalized values
        }
        out[bi] = o;
    }
}

// ---------------- launcher --------------------------------------------------
extern "C" void kernel_launch(void* const* d_in, const int* in_sizes, int n_in,
                              void* d_out, int out_size)
{
    const float* x     = (const float*)d_in[0];
    const int*   o_enc = (const int*)  d_in[1];
    const float* r_enc = (const float*)d_in[2];
    const float* Wq    = (const float*)d_in[3];
    const float* bq    = (const float*)d_in[4];
    const float* Wk    = (const float*)d_in[5];
    const float* bk    = (const float*)d_in[6];
    const float* Wv    = (const float*)d_in[7];
    const float* bv    = (const float*)d_in[8];
    const float* Er    = (const float*)d_in[9];
    const float* W1    = (const float*)d_in[10];
    const float* b1    = (const float*)d_in[11];
    const float* W2    = (const float*)d_in[12];
    const float* b2    = (const float*)d_in[13];
    const float* We    = (const float*)d_in[14];
    const float* be    = (const float*)d_in[15];
    float* out = (float*)d_out;

    cudaFuncSetAttribute(attn_ffn_kernel,
                         cudaFuncAttributeMaxDynamicSharedMemorySize,
                         SMEM_FLOATS * 4);

    attn_ffn_kernel<<<NTOK, 256, SMEM_FLOATS * 4>>>(
        x, Wq, bq, Wk, bk, Wv, bv, Er, W1, b1, W2, b2);

    dim3 g2(EMBc / GBN, NTOK / GBM);   // (4, 32) = 128 blocks
    we_gemm_kernel<<<g2, 256>>>(We, be);

    stats_kernel<<<1, 32>>>();

    final_kernel<<<NTOK, 256>>>(o_enc, r_enc, out);
}

// round 4
// speedup vs baseline: 1.2950x; 1.2950x over previous
#include <cuda_runtime.h>
#include <math.h>

#define NTOK 4096          // B*T
#define TT   1024
#define Fc   6144          // SW*FB
#define EMBc 512

typedef unsigned long long u64;

// ---------------- packed f32x2 helpers (FFMA2 path) -------------------------
__device__ __forceinline__ void fma2(u64 &d, u64 a, u64 b) {
    asm("fma.rn.f32x2 %0, %1, %2, %0;" : "+l"(d) : "l"(a), "l"(b));
}
__device__ __forceinline__ u64 dup2(float x) {
    u64 r; asm("mov.b64 %0, {%1, %1};" : "=l"(r) : "f"(x)); return r;
}
__device__ __forceinline__ u64 pk2(float lo, float hi) {
    u64 r; asm("mov.b64 %0, {%1, %2};" : "=l"(r) : "f"(lo), "f"(hi)); return r;
}
__device__ __forceinline__ float2 up2(u64 v) {
    float2 p; asm("mov.b64 {%0, %1}, %2;" : "=f"(p.x), "=f"(p.y) : "l"(v)); return p;
}
__device__ __forceinline__ float hsum2(u64 v) { float2 p = up2(v); return p.x + p.y; }

// ---------------- scratch ---------------------------------------------------
__device__ float  g_mid[(size_t)NTOK * Fc];
__device__ float  g_emb[(size_t)NTOK * EMBc];
__device__ double g_part[256];
__device__ float  g_stats[2];

// ---------------- kernel 1: per-token rel-attention + FFN -------------------
// shared regions (floats):
//   A : 6208  xr(64x97) -> S(64x66) -> W1 tile(96x64)/W2 tile(64x96) -> out(64x97)
//   Q : 6144  q (stride 96) -> attention output (in place, per head)
//   K : 6144  k pair-interleaved: [(d>>1)*128 + 2*m] = {k[m][d], k[m][d+1]}
//   V : 6208  v (stride 97)
//   B : 4160  W stage(96x32) -> er(64x34) -> hid(64x65)
#define OFF_A 0
#define OFF_Q 6208
#define OFF_K 12352
#define OFF_V 18496
#define OFF_B 24704
#define SMEM_FLOATS 28864   // 115456 bytes -> 2 CTAs/SM

__global__ __launch_bounds__(256, 2) void attn_ffn_kernel(
    const float* __restrict__ x,
    const float* __restrict__ Wq, const float* __restrict__ bq,
    const float* __restrict__ Wk, const float* __restrict__ bk,
    const float* __restrict__ Wv, const float* __restrict__ bv,
    const float* __restrict__ Er,
    const float* __restrict__ W1, const float* __restrict__ b1,
    const float* __restrict__ W2, const float* __restrict__ b2)
{
    extern __shared__ float sm[];
    float* sA = sm + OFF_A;
    float* sQ = sm + OFF_Q;
    float* sK = sm + OFF_K;
    float* sV = sm + OFF_V;
    float* sB = sm + OFF_B;

    const int tid = threadIdx.x;
    const int n   = blockIdx.x;
    const size_t base = (size_t)n * Fc;

    // stage xr[l][d] = x[n, d*64 + l]
    for (int idx = tid; idx < Fc; idx += 256) {
        int d = idx >> 6, l = idx & 63;
        sA[l * 97 + d] = x[base + idx];
    }

    // ---- QKV: (64x96)@(96x96), weights staged in 96x32 tiles, f32x2 --------
    const float* Wm[3] = {Wq, Wk, Wv};
    const float* bm[3] = {bq, bk, bv};
    const int r0 = (tid >> 4) * 4;      // 16 row groups * 4 rows
    const int cc = (tid & 15) * 2;      // 16 col groups * 2 cols (within 32-tile)
    for (int w = 0; w < 3; ++w) {
        for (int ct = 0; ct < 3; ++ct) {
            __syncthreads();
            for (int idx = tid; idx < 3072; idx += 256) {
                int i = idx >> 5, c = idx & 31;
                sB[idx] = Wm[w][i * 96 + ct * 32 + c];
            }
            __syncthreads();
            u64 acc[4] = {0, 0, 0, 0};
            #pragma unroll 4
            for (int i = 0; i < 96; ++i) {
                u64 wp = *(const u64*)&sB[i * 32 + cc];
                #pragma unroll
                for (int r = 0; r < 4; ++r)
                    fma2(acc[r], dup2(sA[(r0 + r) * 97 + i]), wp);
            }
            int col = ct * 32 + cc;
            float bb0 = bm[w][col], bb1 = bm[w][col + 1];
            #pragma unroll
            for (int r = 0; r < 4; ++r) {
                float2 p = up2(acc[r]);
                p.x += bb0; p.y += bb1;
                int row = r0 + r;
                if (w == 0) {
                    *(u64*)&sQ[row * 96 + col] = pk2(p.x, p.y);
                } else if (w == 1) {
                    *(u64*)&sK[(col >> 1) * 128 + 2 * row] = pk2(p.x, p.y);
                } else {
                    sV[row * 97 + col]     = p.x;
                    sV[row * 97 + col + 1] = p.y;
                }
            }
        }
    }
    __syncthreads();

    // er[j][d] into B (stride 34)
    for (int idx = tid; idx < 2048; idx += 256) {
        int j = idx >> 5, d = idx & 31;
        sB[j * 34 + d] = Er[idx];
    }
    __syncthreads();

    // ---- relative attention ------------------------------------------------
    const float scale = 0.17677669529663687f;   // 1/sqrt(32)
    const int wid = tid >> 5, lane = tid & 31;
    const int l0 = (tid >> 4) * 4, m0 = (tid & 15) * 4;
    const int oc0 = (tid & 15) * 2;
    // srel[l][m] = qer[l][m+63-l] (m<=l); with r,c tile: j = (m0-l0+60) + (c-r+3)
    int jr[7];
    {
        int jb = m0 - l0 + 60;
        #pragma unroll
        for (int t = 0; t < 7; ++t) jr[t] = min(max(jb + t, 0), 63);
    }

    for (int h = 0; h < 3; ++h) {
        const int hb = h * 32;
        // combined score: S + Srel accumulated together, pair over d
        u64 acc[4][4];
        #pragma unroll
        for (int r = 0; r < 4; ++r)
            #pragma unroll
            for (int c = 0; c < 4; ++c) acc[r][c] = 0;
        #pragma unroll 2
        for (int dp = 0; dp < 16; ++dp) {
            int d = 2 * dp;
            u64 qp[4], kp[4], ep[7];
            #pragma unroll
            for (int r = 0; r < 4; ++r) qp[r] = *(const u64*)&sQ[(l0 + r) * 96 + hb + d];
            #pragma unroll
            for (int c = 0; c < 4; ++c) kp[c] = *(const u64*)&sK[((hb + d) >> 1) * 128 + 2 * (m0 + c)];
            #pragma unroll
            for (int t = 0; t < 7; ++t) ep[t] = *(const u64*)&sB[jr[t] * 34 + d];
            #pragma unroll
            for (int r = 0; r < 4; ++r)
                #pragma unroll
                for (int c = 0; c < 4; ++c) {
                    fma2(acc[r][c], qp[r], kp[c]);
                    fma2(acc[r][c], qp[r], ep[c - r + 3]);
                }
        }
        #pragma unroll
        for (int r = 0; r < 4; ++r)
            #pragma unroll
            for (int c = 0; c < 4; ++c)
                sA[(l0 + r) * 66 + m0 + c] = hsum2(acc[r][c]);
        __syncthreads();

        // softmax (warp per row, causal mask, scale)
        for (int l = wid; l < 64; l += 8) {
            int m1 = lane + 32;
            float v0 = (lane <= l) ? sA[l * 66 + lane] * scale : -1e30f;
            float v1 = (m1   <= l) ? sA[l * 66 + m1]   * scale : -1e30f;
            float mx = fmaxf(v0, v1);
            #pragma unroll
            for (int o = 16; o; o >>= 1) mx = fmaxf(mx, __shfl_xor_sync(0xffffffffu, mx, o));
            float e0 = __expf(v0 - mx), e1 = __expf(v1 - mx);
            float ssum = e0 + e1;
            #pragma unroll
            for (int o = 16; o; o >>= 1) ssum += __shfl_xor_sync(0xffffffffu, ssum, o);
            float inv = 1.0f / ssum;
            sA[l * 66 + lane] = e0 * inv;
            sA[l * 66 + m1]   = e1 * inv;
        }
        __syncthreads();

        // O = P @ V : pair over m; output overwrites q columns of this head
        u64 po[4][2];
        #pragma unroll
        for (int r = 0; r < 4; ++r) { po[r][0] = 0; po[r][1] = 0; }
        #pragma unroll 2
        for (int mp = 0; mp < 32; ++mp) {
            u64 pv[4], vv[2];
            #pragma unroll
            for (int r = 0; r < 4; ++r) pv[r] = *(const u64*)&sA[(l0 + r) * 66 + 2 * mp];
            #pragma unroll
            for (int c = 0; c < 2; ++c)
                vv[c] = pk2(sV[(2 * mp) * 97 + hb + oc0 + c],
                            sV[(2 * mp + 1) * 97 + hb + oc0 + c]);
            #pragma unroll
            for (int r = 0; r < 4; ++r)
                #pragma unroll
                for (int c = 0; c < 2; ++c) fma2(po[r][c], pv[r], vv[c]);
        }
        __syncthreads();   // P (in sA) fully consumed before next head's scores land
        #pragma unroll
        for (int r = 0; r < 4; ++r)
            #pragma unroll
            for (int c = 0; c < 2; ++c)
                sQ[(l0 + r) * 96 + hb + oc0 + c] = hsum2(po[r][c]);
    }
    __syncthreads();

    // ---- FFN: 6 tiles of 64 hidden cols; GEMM2 acc kept in registers -------
    const int fr0 = (tid >> 4) * 4;
    const int fc0 = (tid & 15) * 4;
    const int gc0 = (tid & 15) * 6;
    u64 acc2[4][3];
    #pragma unroll
    for (int r = 0; r < 4; ++r)
        #pragma unroll
        for (int c = 0; c < 3; ++c) acc2[r][c] = 0;

    for (int jt = 0; jt < 6; ++jt) {
        __syncthreads();
        for (int idx = tid; idx < 6144; idx += 256) {   // W1 tile 96x64 -> A
            int i = idx >> 6, c = idx & 63;
            sA[idx] = W1[i * 384 + jt * 64 + c];
        }
        __syncthreads();
        u64 ha[4][2];
        #pragma unroll
        for (int r = 0; r < 4; ++r) { ha[r][0] = 0; ha[r][1] = 0; }
        #pragma unroll 2
        for (int i = 0; i < 96; ++i) {
            u64 w0 = *(const u64*)&sA[i * 64 + fc0];
            u64 w1 = *(const u64*)&sA[i * 64 + fc0 + 2];
            #pragma unroll
            for (int r = 0; r < 4; ++r) {
                u64 a = dup2(sQ[(fr0 + r) * 96 + i]);
                fma2(ha[r][0], a, w0);
                fma2(ha[r][1], a, w1);
            }
        }
        float bb[4];
        #pragma unroll
        for (int c = 0; c < 4; ++c) bb[c] = b1[jt * 64 + fc0 + c];
        #pragma unroll
        for (int r = 0; r < 4; ++r) {
            float2 p0 = up2(ha[r][0]), p1 = up2(ha[r][1]);
            sB[(fr0 + r) * 65 + fc0 + 0] = fmaxf(p0.x + bb[0], 0.f);
            sB[(fr0 + r) * 65 + fc0 + 1] = fmaxf(p0.y + bb[1], 0.f);
            sB[(fr0 + r) * 65 + fc0 + 2] = fmaxf(p1.x + bb[2], 0.f);
            sB[(fr0 + r) * 65 + fc0 + 3] = fmaxf(p1.y + bb[3], 0.f);
        }
        __syncthreads();
        for (int idx = tid; idx < 6144; idx += 256) {   // W2 tile 64x96 -> A
            int k = idx / 96, c = idx - k * 96;
            sA[idx] = W2[(jt * 64 + k) * 96 + c];
        }
        __syncthreads();
        #pragma unroll 2
        for (int k = 0; k < 64; ++k) {
            u64 w2a = *(const u64*)&sA[k * 96 + gc0];
            u64 w2b = *(const u64*)&sA[k * 96 + gc0 + 2];
            u64 w2c = *(const u64*)&sA[k * 96 + gc0 + 4];
            #pragma unroll
            for (int r = 0; r < 4; ++r) {
                u64 hv = dup2(sB[(fr0 + r) * 65 + k]);
                fma2(acc2[r][0], hv, w2a);
                fma2(acc2[r][1], hv, w2b);
                fma2(acc2[r][2], hv, w2c);
            }
        }
    }
    __syncthreads();
    float b2v[6];
    #pragma unroll
    for (int c = 0; c < 6; ++c) b2v[c] = b2[gc0 + c];
    #pragma unroll
    for (int r = 0; r < 4; ++r)
        #pragma unroll
        for (int cp = 0; cp < 3; ++cp) {
            float2 p = up2(acc2[r][cp]);
            sA[(fr0 + r) * 97 + gc0 + 2 * cp]     = p.x + b2v[2 * cp];
            sA[(fr0 + r) * 97 + gc0 + 2 * cp + 1] = p.y + b2v[2 * cp + 1];
        }
    __syncthreads();
    // transpose back: mid[n, d*64 + l] = out[l][d], coalesced
    for (int idx = tid; idx < Fc; idx += 256) {
        int d = idx >> 6, l = idx & 63;
        g_mid[base + idx] = sA[l * 97 + d];
    }
}

// ---------------- kernel 2: (4096x6144)@(6144x512)+be, f32x2, 512 thr -------
__global__ __launch_bounds__(512) void we_gemm_kernel(
    const float* __restrict__ We, const float* __restrict__ be)
{
    __shared__ float As[16 * 128];   // As[k][m]
    __shared__ float Bs[16 * 128];   // Bs[k][c]
    __shared__ double red[32];

    const int tid = threadIdx.x;
    const int e0 = blockIdx.x * 128;
    const int n0 = blockIdx.y * 128;
    const int r0 = (tid >> 5) * 8;      // warp -> 8 rows (broadcast A loads)
    const int c0 = (tid & 31) * 4;      // lane -> 4 cols (conflict-free)

    u64 acc[4][4];                      // [rowpair][col]
    #pragma unroll
    for (int i = 0; i < 4; ++i)
        #pragma unroll
        for (int j = 0; j < 4; ++j) acc[i][j] = 0;

    for (int k0 = 0; k0 < Fc; k0 += 16) {
        __syncthreads();
        {
            int m = tid >> 2, kq = (tid & 3) * 4;
            float4 v = *(const float4*)&g_mid[(size_t)(n0 + m) * Fc + k0 + kq];
            As[(kq + 0) * 128 + m] = v.x;
            As[(kq + 1) * 128 + m] = v.y;
            As[(kq + 2) * 128 + m] = v.z;
            As[(kq + 3) * 128 + m] = v.w;
        }
        #pragma unroll
        for (int q = 0; q < 4; ++q) {
            int idx = tid + q * 512;
            int k = idx >> 7, c = idx & 127;
            Bs[idx] = We[(size_t)(k0 + k) * EMBc + e0 + c];
        }
        __syncthreads();
        #pragma unroll
        for (int k = 0; k < 16; ++k) {
            ulonglong2 a01 = *(const ulonglong2*)&As[k * 128 + r0];
            ulonglong2 a23 = *(const ulonglong2*)&As[k * 128 + r0 + 4];
            u64 ap[4] = {a01.x, a01.y, a23.x, a23.y};
            float4 bv = *(const float4*)&Bs[k * 128 + c0];
            u64 bd[4] = {dup2(bv.x), dup2(bv.y), dup2(bv.z), dup2(bv.w)};
            #pragma unroll
            for (int i = 0; i < 4; ++i)
                #pragma unroll
                for (int j = 0; j < 4; ++j) fma2(acc[i][j], ap[i], bd[j]);
        }
    }

    float beb[4];
    #pragma unroll
    for (int j = 0; j < 4; ++j) beb[j] = be[e0 + c0 + j];

    double s = 0.0, s2 = 0.0;
    #pragma unroll
    for (int i = 0; i < 4; ++i) {
        float4 o0, o1;
        float2 p0 = up2(acc[i][0]), p1 = up2(acc[i][1]);
        float2 p2 = up2(acc[i][2]), p3 = up2(acc[i][3]);
        o0.x = p0.x + beb[0]; o0.y = p1.x + beb[1]; o0.z = p2.x + beb[2]; o0.w = p3.x + beb[3];
        o1.x = p0.y + beb[0]; o1.y = p1.y + beb[1]; o1.z = p2.y + beb[2]; o1.w = p3.y + beb[3];
        int row0 = n0 + r0 + 2 * i;
        *(float4*)&g_emb[(size_t)row0 * EMBc + e0 + c0]       = o0;
        *(float4*)&g_emb[(size_t)(row0 + 1) * EMBc + e0 + c0] = o1;
        s  += (double)o0.x + o0.y + o0.z + o0.w + (double)o1.x + o1.y + o1.z + o1.w;
        s2 += (double)o0.x * o0.x + (double)o0.y * o0.y + (double)o0.z * o0.z + (double)o0.w * o0.w
            + (double)o1.x * o1.x + (double)o1.y * o1.y + (double)o1.z * o1.z + (double)o1.w * o1.w;
    }
    #pragma unroll
    for (int o = 16; o; o >>= 1) {
        s  += __shfl_xor_sync(0xffffffffu, s, o);
        s2 += __shfl_xor_sync(0xffffffffu, s2, o);
    }
    const int wrp = tid >> 5, lane = tid & 31;
    if (lane == 0) { red[wrp] = s; red[wrp + 16] = s2; }
    __syncthreads();
    if (tid == 0) {
        double ts = 0.0, ts2 = 0.0;
        #pragma unroll
        for (int i = 0; i < 16; ++i) { ts += red[i]; ts2 += red[i + 16]; }
        int bid = blockIdx.y * gridDim.x + blockIdx.x;   // < 128
        g_part[bid * 2]     = ts;
        g_part[bid * 2 + 1] = ts2;
    }
}

// ---------------- kernel 3: finalize mean / rstd ----------------------------
__global__ void stats_kernel()
{
    if (threadIdx.x == 0) {
        double s = 0.0, s2 = 0.0;
        for (int i = 0; i < 128; ++i) { s += g_part[2 * i]; s2 += g_part[2 * i + 1]; }
        double cnt = (double)NTOK * (double)EMBc;
        double mu  = s / cnt;
        double var = s2 / cnt - mu * mu;
        g_stats[0] = (float)mu;
        g_stats[1] = (float)(1.0 / sqrt(var + 1e-8));
    }
}

// ---------------- kernel 4: normalize + segment means + residual ------------
__global__ __launch_bounds__(256) void final_kernel(
    const int* __restrict__ o_enc, const float* __restrict__ r_enc,
    float* __restrict__ out)
{
    const int n = blockIdx.x;
    const int b = n >> 10, t = n & 1023;
    __shared__ int s_len;
    if (threadIdx.x == 0) {
        int len = 0;
        bool is_start = (t == 0) || (o_enc[n] != 0);
        if (is_start) {
            int tt = t + 1;
            while (tt < TT && o_enc[b * TT + tt] == 0) ++tt;
            len = tt - t;
        }
        s_len = len;
    }
    __syncthreads();
    const float mu = g_stats[0], rs = g_stats[1];
    const int len = s_len;
    for (int e = threadIdx.x; e < EMBc; e += 256) {
        size_t bi = (size_t)n * EMBc + e;
        float v = (g_emb[bi] - mu) * rs;
        float o = v + r_enc[bi];
        if (len) {
            float sum = 0.f;
            for (int s = 0; s < len; ++s)
                sum += g_emb[(size_t)(n + s) * EMBc + e];
            o += (sum / (float)len - mu) * rs;
        }
        out[bi] = o;
    }
}

// ---------------- launcher --------------------------------------------------
extern "C" void kernel_launch(void* const* d_in, const int* in_sizes, int n_in,
                              void* d_out, int out_size)
{
    const float* x     = (const float*)d_in[0];
    const int*   o_enc = (const int*)  d_in[1];
    const float* r_enc = (const float*)d_in[2];
    const float* Wq    = (const float*)d_in[3];
    const float* bq    = (const float*)d_in[4];
    const float* Wk    = (const float*)d_in[5];
    const float* bk    = (const float*)d_in[6];
    const float* Wv    = (const float*)d_in[7];
    const float* bv    = (const float*)d_in[8];
    const float* Er    = (const float*)d_in[9];
    const float* W1    = (const float*)d_in[10];
    const float* b1    = (const float*)d_in[11];
    const float* W2    = (const float*)d_in[12];
    const float* b2    = (const float*)d_in[13];
    const float* We    = (const float*)d_in[14];
    const float* be    = (const float*)d_in[15];
    float* out = (float*)d_out;

    cudaFuncSetAttribute(attn_ffn_kernel,
                         cudaFuncAttributeMaxDynamicSharedMemorySize,
                         SMEM_FLOATS * 4);

    attn_ffn_kernel<<<NTOK, 256, SMEM_FLOATS * 4>>>(
        x, Wq, bq, Wk, bk, Wv, bv, Er, W1, b1, W2, b2);

    dim3 g2(EMBc / 128, NTOK / 128);   // (4, 32) = 128 blocks
    we_gemm_kernel<<<g2, 512>>>(We, be);

    stats_kernel<<<1, 32>>>();

    final_kernel<<<NTOK, 256>>>(o_enc, r_enc, out);
}

// round 5
// speedup vs baseline: 1.3053x; 1.0079x over previous
#include <cuda_runtime.h>
#include <math.h>

#define NTOK 4096          // B*T
#define TT   1024
#define Fc   6144          // SW*FB = 96*64
#define EMBc 512

typedef unsigned long long u64;

// ---------------- packed f32x2 helpers (FFMA2 path) -------------------------
__device__ __forceinline__ void fma2(u64 &d, u64 a, u64 b) {
    asm("fma.rn.f32x2 %0, %1, %2, %0;" : "+l"(d) : "l"(a), "l"(b));
}
__device__ __forceinline__ u64 dup2(float x) {
    u64 r; asm("mov.b64 %0, {%1, %1};" : "=l"(r) : "f"(x)); return r;
}
__device__ __forceinline__ float2 up2(u64 v) {
    float2 p; asm("mov.b64 {%0, %1}, %2;" : "=f"(p.x), "=f"(p.y) : "l"(v)); return p;
}
__device__ __forceinline__ float hsum2(u64 v) { float2 p = up2(v); return p.x + p.y; }

// ---------------- scratch ---------------------------------------------------
__device__ float  g_q[(size_t)NTOK * Fc];     // [(n,l), d]
__device__ float  g_kT[(size_t)NTOK * Fc];    // [n][d][m]
__device__ float  g_vT[(size_t)NTOK * Fc];    // [n][d][m]
__device__ float  g_attT[(size_t)NTOK * Fc];  // [n][d][l]
__device__ float  g_mid[(size_t)NTOK * Fc];   // (B,T,F)
__device__ float  g_emb[(size_t)NTOK * EMBc];
__device__ double g_part[256];
__device__ float  g_stats[2];

// ---------------- kernel 1: batched QKV GEMM --------------------------------
// grid (2048, 3): 128-row tiles (2 tokens), blockIdx.y = matrix (Q/K/V)
// smem: As 12416 (A-tile [d*128+m], reused as transpose bounce [c*129+m])
//       Ws 9216  (weight [d*96+c])
#define QKV_SMEM (12416 + 9216)

__global__ __launch_bounds__(512, 2) void qkv_kernel(
    const float* __restrict__ x,
    const float* __restrict__ Wq, const float* __restrict__ bq,
    const float* __restrict__ Wk, const float* __restrict__ bk,
    const float* __restrict__ Wv, const float* __restrict__ bv)
{
    extern __shared__ float sm[];
    float* As = sm;
    float* Ws = sm + 12416;

    const int tid = threadIdx.x;
    const int mat = blockIdx.y;
    const int n0  = blockIdx.x * 2;
    const size_t xbase = (size_t)n0 * Fc;

    const float* W  = (mat == 0) ? Wq : (mat == 1) ? Wk : Wv;
    const float* bi = (mat == 0) ? bq : (mat == 1) ? bk : bv;

    // A-tile: As[d*128+m] = xr[(n0+(m>>6))][m&63][d] = x[n, d*64 + l]
    for (int idx = tid; idx < 12288; idx += 512) {
        int d = idx >> 7, m = idx & 127;
        As[idx] = x[xbase + (size_t)(m >> 6) * Fc + d * 64 + (m & 63)];
    }
    for (int idx = tid; idx < 9216; idx += 512) Ws[idx] = W[idx];
    __syncthreads();

    const int r0 = (tid >> 5) * 8;     // warp -> 8 rows
    const int lane = tid & 31;         // lane -> cols {lane, lane+32, lane+64}
    u64 acc[4][3];
    #pragma unroll
    for (int i = 0; i < 4; ++i)
        #pragma unroll
        for (int j = 0; j < 3; ++j) acc[i][j] = 0;

    #pragma unroll 2
    for (int d = 0; d < 96; ++d) {
        ulonglong2 a01 = *(const ulonglong2*)&As[d * 128 + r0];
        ulonglong2 a23 = *(const ulonglong2*)&As[d * 128 + r0 + 4];
        u64 ap[4] = {a01.x, a01.y, a23.x, a23.y};
        u64 w0 = dup2(Ws[d * 96 + lane]);
        u64 w1 = dup2(Ws[d * 96 + lane + 32]);
        u64 w2 = dup2(Ws[d * 96 + lane + 64]);
        #pragma unroll
        for (int i = 0; i < 4; ++i) {
            fma2(acc[i][0], ap[i], w0);
            fma2(acc[i][1], ap[i], w1);
            fma2(acc[i][2], ap[i], w2);
        }
    }
    float bb[3] = {bi[lane], bi[lane + 32], bi[lane + 64]};

    if (mat == 0) {
        // Q: direct store, rows contiguous: g_q[(n0*64 + m)*96 + c]
        #pragma unroll
        for (int i = 0; i < 4; ++i)
            #pragma unroll
            for (int j = 0; j < 3; ++j) {
                float2 p = up2(acc[i][j]);
                int row = r0 + 2 * i, col = lane + 32 * j;
                g_q[xbase + (size_t)row * 96 + col]       = p.x + bb[j];
                g_q[xbase + (size_t)(row + 1) * 96 + col] = p.y + bb[j];
            }
    } else {
        // K/V: bounce-transpose in smem then coalesced store to [n][d][m]
        __syncthreads();
        #pragma unroll
        for (int i = 0; i < 4; ++i)
            #pragma unroll
            for (int j = 0; j < 3; ++j) {
                float2 p = up2(acc[i][j]);
                int col = lane + 32 * j, row = r0 + 2 * i;
                As[col * 129 + row]     = p.x + bb[j];
                As[col * 129 + row + 1] = p.y + bb[j];
            }
        __syncthreads();
        float* gout = (mat == 1) ? g_kT : g_vT;
        for (int idx = tid; idx < 12288; idx += 512) {
            int d = idx >> 7, m = idx & 127;
            gout[xbase + (size_t)(m >> 6) * Fc + d * 64 + (m & 63)] = As[d * 129 + m];
        }
    }
}

// ---------------- kernel 2: per-token attention -----------------------------
// smem floats: Q 6208 (stride 97) | KT 6144 | VT 6144 | ErT 2112 | S 4096 | R 4096
#define ATT_SMEM 28800

__global__ __launch_bounds__(256, 2) void attn_kernel(const float* __restrict__ Er)
{
    extern __shared__ float sm[];
    float* sQ  = sm;             // [l*97 + d]; PV output overwrites per head
    float* sKT = sm + 6208;      // [d*64 + m]
    float* sVT = sKT + 6144;     // [d*64 + m]
    float* sEr = sVT + 6144;     // [d*66 + j]
    float* sS  = sEr + 2112;     // [l*64 + m]
    float* sR  = sS + 4096;      // [l*64 + j]

    const int tid = threadIdx.x;
    const int n   = blockIdx.x;
    const size_t base = (size_t)n * Fc;

    for (int idx = tid; idx < Fc; idx += 256) {
        int l = idx / 96, d = idx - l * 96;
        sQ[l * 97 + d] = g_q[base + idx];
    }
    for (int idx = tid; idx < Fc; idx += 256) sKT[idx] = g_kT[base + idx];
    for (int idx = tid; idx < Fc; idx += 256) sVT[idx] = g_vT[base + idx];
    for (int idx = tid; idx < 2048; idx += 256) {
        int j = idx >> 5, d = idx & 31;
        sEr[d * 66 + j] = Er[idx];
    }
    __syncthreads();

    const float scale = 0.17677669529663687f;   // 1/sqrt(32)
    const int wid = tid >> 5, lane = tid & 31;
    const int l0 = (tid >> 4) * 4, m0 = (tid & 15) * 4;
    const int d0 = (tid & 15) * 2;

    for (int h = 0; h < 3; ++h) {
        const int hb = h * 32;
        // S[l][m] = sum_d q[l][hb+d] k[m][hb+d]   (pairs over m via kT)
        // R[l][j] = sum_d q[l][hb+d] Er[j][d]     (pairs over j via ErT)
        u64 aS[4][2], aR[4][2];
        #pragma unroll
        for (int r = 0; r < 4; ++r) { aS[r][0]=0; aS[r][1]=0; aR[r][0]=0; aR[r][1]=0; }
        #pragma unroll 2
        for (int d = 0; d < 32; ++d) {
            u64 k0 = *(const u64*)&sKT[(hb + d) * 64 + m0];
            u64 k1 = *(const u64*)&sKT[(hb + d) * 64 + m0 + 2];
            u64 e0 = *(const u64*)&sEr[d * 66 + m0];
            u64 e1 = *(const u64*)&sEr[d * 66 + m0 + 2];
            #pragma unroll
            for (int r = 0; r < 4; ++r) {
                u64 q = dup2(sQ[(l0 + r) * 97 + hb + d]);
                fma2(aS[r][0], q, k0); fma2(aS[r][1], q, k1);
                fma2(aR[r][0], q, e0); fma2(aR[r][1], q, e1);
            }
        }
        #pragma unroll
        for (int r = 0; r < 4; ++r) {
            *(u64*)&sS[(l0 + r) * 64 + m0]     = aS[r][0];
            *(u64*)&sS[(l0 + r) * 64 + m0 + 2] = aS[r][1];
            *(u64*)&sR[(l0 + r) * 64 + m0]     = aR[r][0];
            *(u64*)&sR[(l0 + r) * 64 + m0 + 2] = aR[r][1];
        }
        __syncthreads();

        // softmax with skew: srel[l][m] = R[l][m+63-l] for m<=l
        for (int l = wid; l < 64; l += 8) {
            int m1 = lane + 32;
            int j0 = min(lane + 63 - l, 63);
            int j1 = min(m1 + 63 - l, 63);
            float v0 = (lane <= l) ? (sS[l * 64 + lane] + sR[l * 64 + j0]) * scale : -1e30f;
            float v1 = (m1   <= l) ? (sS[l * 64 + m1]   + sR[l * 64 + j1]) * scale : -1e30f;
            float mx = fmaxf(v0, v1);
            #pragma unroll
            for (int o = 16; o; o >>= 1) mx = fmaxf(mx, __shfl_xor_sync(0xffffffffu, mx, o));
            float e0 = __expf(v0 - mx), e1 = __expf(v1 - mx);
            float ssum = e0 + e1;
            #pragma unroll
            for (int o = 16; o; o >>= 1) ssum += __shfl_xor_sync(0xffffffffu, ssum, o);
            float inv = 1.0f / ssum;
            sS[l * 64 + lane] = e0 * inv;
            sS[l * 64 + m1]   = e1 * inv;
        }
        __syncthreads();

        // O = P @ V (pairs over m via vT); write into sQ columns of this head
        u64 po[4][2];
        #pragma unroll
        for (int r = 0; r < 4; ++r) { po[r][0] = 0; po[r][1] = 0; }
        #pragma unroll 2
        for (int mp = 0; mp < 32; ++mp) {
            u64 v0 = *(const u64*)&sVT[(hb + d0) * 64 + 2 * mp];
            u64 v1 = *(const u64*)&sVT[(hb + d0 + 1) * 64 + 2 * mp];
            #pragma unroll
            for (int r = 0; r < 4; ++r) {
                u64 pv = *(const u64*)&sS[(l0 + r) * 64 + 2 * mp];
                fma2(po[r][0], pv, v0);
                fma2(po[r][1], pv, v1);
            }
        }
        __syncthreads();   // P fully consumed before next head's S overwrites sS
        #pragma unroll
        for (int r = 0; r < 4; ++r) {
            sQ[(l0 + r) * 97 + hb + d0]     = hsum2(po[r][0]);
            sQ[(l0 + r) * 97 + hb + d0 + 1] = hsum2(po[r][1]);
        }
    }
    __syncthreads();
    // write out token-transposed: g_attT[n][d][l]
    for (int idx = tid; idx < Fc; idx += 256) {
        int d = idx >> 6, l = idx & 63;
        g_attT[base + idx] = sQ[l * 97 + d];
    }
}

// ---------------- kernel 3: fused FFN (96->384->96) over 128-row tiles ------
// smem: sX 96*132=12672 | sW 9216 | sH 96*132=12672   = 34560 floats (138 KB)
#define FFN_SMEM (12672 + 9216 + 12672)

__global__ __launch_bounds__(512) void ffn_kernel(
    const float* __restrict__ W1, const float* __restrict__ b1,
    const float* __restrict__ W2, const float* __restrict__ b2)
{
    extern __shared__ float sm[];
    float* sX = sm;            // att tile [d*132 + m]
    float* sW = sm + 12672;    // W1c / W2c alternating [k*96 + c]
    float* sH = sW + 9216;     // h chunk [c*132 + m]; reused as out bounce

    const int tid = threadIdx.x;
    const int n0  = blockIdx.x * 2;
    const size_t base = (size_t)n0 * Fc;

    for (int idx = tid; idx < 12288; idx += 512) {
        int d = idx >> 7, m = idx & 127;
        sX[d * 132 + m] = g_attT[base + (size_t)(m >> 6) * Fc + d * 64 + (m & 63)];
    }

    const int r0 = (tid >> 5) * 8;
    const int lane = tid & 31;
    u64 acc2[4][3];
    #pragma unroll
    for (int i = 0; i < 4; ++i)
        #pragma unroll
        for (int j = 0; j < 3; ++j) acc2[i][j] = 0;
    float bb2[3] = {b2[lane], b2[lane + 32], b2[lane + 64]};

    for (int ch = 0; ch < 4; ++ch) {
        __syncthreads();
        for (int idx = tid; idx < 9216; idx += 512) {
            int d = idx / 96, c = idx - d * 96;
            sW[idx] = W1[d * 384 + ch * 96 + c];
        }
        __syncthreads();
        u64 ha[4][3];
        #pragma unroll
        for (int i = 0; i < 4; ++i)
            #pragma unroll
            for (int j = 0; j < 3; ++j) ha[i][j] = 0;
        #pragma unroll 2
        for (int d = 0; d < 96; ++d) {
            ulonglong2 a01 = *(const ulonglong2*)&sX[d * 132 + r0];
            ulonglong2 a23 = *(const ulonglong2*)&sX[d * 132 + r0 + 4];
            u64 ap[4] = {a01.x, a01.y, a23.x, a23.y};
            u64 w0 = dup2(sW[d * 96 + lane]);
            u64 w1 = dup2(sW[d * 96 + lane + 32]);
            u64 w2 = dup2(sW[d * 96 + lane + 64]);
            #pragma unroll
            for (int i = 0; i < 4; ++i) {
                fma2(ha[i][0], ap[i], w0);
                fma2(ha[i][1], ap[i], w1);
                fma2(ha[i][2], ap[i], w2);
            }
        }
        float bb1[3] = {b1[ch * 96 + lane], b1[ch * 96 + lane + 32], b1[ch * 96 + lane + 64]};
        #pragma unroll
        for (int i = 0; i < 4; ++i)
            #pragma unroll
            for (int j = 0; j < 3; ++j) {
                float2 p = up2(ha[i][j]);
                int c = lane + 32 * j, row = r0 + 2 * i;
                sH[c * 132 + row]     = fmaxf(p.x + bb1[j], 0.f);
                sH[c * 132 + row + 1] = fmaxf(p.y + bb1[j], 0.f);
            }
        __syncthreads();
        for (int idx = tid; idx < 9216; idx += 512) {
            int k = idx / 96, c = idx - k * 96;
            sW[idx] = W2[(ch * 96 + k) * 96 + c];
        }
        __syncthreads();
        #pragma unroll 2
        for (int k = 0; k < 96; ++k) {
            ulonglong2 a01 = *(const ulonglong2*)&sH[k * 132 + r0];
            ulonglong2 a23 = *(const ulonglong2*)&sH[k * 132 + r0 + 4];
            u64 ap[4] = {a01.x, a01.y, a23.x, a23.y};
            u64 w0 = dup2(sW[k * 96 + lane]);
            u64 w1 = dup2(sW[k * 96 + lane + 32]);
            u64 w2 = dup2(sW[k * 96 + lane + 64]);
            #pragma unroll
            for (int i = 0; i < 4; ++i) {
                fma2(acc2[i][0], ap[i], w0);
                fma2(acc2[i][1], ap[i], w1);
                fma2(acc2[i][2], ap[i], w2);
            }
        }
    }
    // epilogue: bounce-transpose then coalesced store to g_mid (B,T,F)
    __syncthreads();
    #pragma unroll
    for (int i = 0; i < 4; ++i)
        #pragma unroll
        for (int j = 0; j < 3; ++j) {
            float2 p = up2(acc2[i][j]);
            int c = lane + 32 * j, row = r0 + 2 * i;
            sH[c * 132 + row]     = p.x + bb2[j];
            sH[c * 132 + row + 1] = p.y + bb2[j];
        }
    __syncthreads();
    for (int idx = tid; idx < 12288; idx += 512) {
        int c = idx >> 7, m = idx & 127;
        g_mid[base + (size_t)(m >> 6) * Fc + c * 64 + (m & 63)] = sH[c * 132 + m];
    }
}

// ---------------- kernel 4: (4096x6144)@(6144x512)+be, f32x2, 512 thr -------
__global__ __launch_bounds__(512) void we_gemm_kernel(
    const float* __restrict__ We, const float* __restrict__ be)
{
    __shared__ float As[16 * 128];
    __shared__ float Bs[16 * 128];
    __shared__ double red[32];

    const int tid = threadIdx.x;
    const int e0 = blockIdx.x * 128;
    const int n0 = blockIdx.y * 128;
    const int r0 = (tid >> 5) * 8;
    const int c0 = (tid & 31) * 4;

    u64 acc[4][4];
    #pragma unroll
    for (int i = 0; i < 4; ++i)
        #pragma unroll
        for (int j = 0; j < 4; ++j) acc[i][j] = 0;

    for (int k0 = 0; k0 < Fc; k0 += 16) {
        __syncthreads();
        {
            int m = tid >> 2, kq = (tid & 3) * 4;
            float4 v = *(const float4*)&g_mid[(size_t)(n0 + m) * Fc + k0 + kq];
            As[(kq + 0) * 128 + m] = v.x;
            As[(kq + 1) * 128 + m] = v.y;
            As[(kq + 2) * 128 + m] = v.z;
            As[(kq + 3) * 128 + m] = v.w;
        }
        #pragma unroll
        for (int q = 0; q < 4; ++q) {
            int idx = tid + q * 512;
            int k = idx >> 7, c = idx & 127;
            Bs[idx] = We[(size_t)(k0 + k) * EMBc + e0 + c];
        }
        __syncthreads();
        #pragma unroll
        for (int k = 0; k < 16; ++k) {
            ulonglong2 a01 = *(const ulonglong2*)&As[k * 128 + r0];
            ulonglong2 a23 = *(const ulonglong2*)&As[k * 128 + r0 + 4];
            u64 ap[4] = {a01.x, a01.y, a23.x, a23.y};
            float4 bv = *(const float4*)&Bs[k * 128 + c0];
            u64 bd[4] = {dup2(bv.x), dup2(bv.y), dup2(bv.z), dup2(bv.w)};
            #pragma unroll
            for (int i = 0; i < 4; ++i)
                #pragma unroll
                for (int j = 0; j < 4; ++j) fma2(acc[i][j], ap[i], bd[j]);
        }
    }

    float beb[4];
    #pragma unroll
    for (int j = 0; j < 4; ++j) beb[j] = be[e0 + c0 + j];

    double s = 0.0, s2 = 0.0;
    #pragma unroll
    for (int i = 0; i < 4; ++i) {
        float4 o0, o1;
        float2 p0 = up2(acc[i][0]), p1 = up2(acc[i][1]);
        float2 p2 = up2(acc[i][2]), p3 = up2(acc[i][3]);
        o0.x = p0.x + beb[0]; o0.y = p1.x + beb[1]; o0.z = p2.x + beb[2]; o0.w = p3.x + beb[3];
        o1.x = p0.y + beb[0]; o1.y = p1.y + beb[1]; o1.z = p2.y + beb[2]; o1.w = p3.y + beb[3];
        int row0 = n0 + r0 + 2 * i;
        *(float4*)&g_emb[(size_t)row0 * EMBc + e0 + c0]       = o0;
        *(float4*)&g_emb[(size_t)(row0 + 1) * EMBc + e0 + c0] = o1;
        s  += (double)o0.x + o0.y + o0.z + o0.w + (double)o1.x + o1.y + o1.z + o1.w;
        s2 += (double)o0.x * o0.x + (double)o0.y * o0.y + (double)o0.z * o0.z + (double)o0.w * o0.w
            + (double)o1.x * o1.x + (double)o1.y * o1.y + (double)o1.z * o1.z + (double)o1.w * o1.w;
    }
    #pragma unroll
    for (int o = 16; o; o >>= 1) {
        s  += __shfl_xor_sync(0xffffffffu, s, o);
        s2 += __shfl_xor_sync(0xffffffffu, s2, o);
    }
    const int wrp = tid >> 5, lane = tid & 31;
    if (lane == 0) { red[wrp] = s; red[wrp + 16] = s2; }
    __syncthreads();
    if (tid == 0) {
        double ts = 0.0, ts2 = 0.0;
        #pragma unroll
        for (int i = 0; i < 16; ++i) { ts += red[i]; ts2 += red[i + 16]; }
        int bid = blockIdx.y * gridDim.x + blockIdx.x;
        g_part[bid * 2]     = ts;
        g_part[bid * 2 + 1] = ts2;
    }
}

// ---------------- kernel 5: finalize mean / rstd ----------------------------
__global__ void stats_kernel()
{
    if (threadIdx.x == 0) {
        double s = 0.0, s2 = 0.0;
        for (int i = 0; i < 128; ++i) { s += g_part[2 * i]; s2 += g_part[2 * i + 1]; }
        double cnt = (double)NTOK * (double)EMBc;
        double mu  = s / cnt;
        double var = s2 / cnt - mu * mu;
        g_stats[0] = (float)mu;
        g_stats[1] = (float)(1.0 / sqrt(var + 1e-8));
    }
}

// ---------------- kernel 6: normalize + segment means + residual ------------
__global__ __launch_bounds__(256) void final_kernel(
    const int* __restrict__ o_enc, const float* __restrict__ r_enc,
    float* __restrict__ out)
{
    const int n = blockIdx.x;
    const int b = n >> 10, t = n & 1023;
    __shared__ int s_len;
    if (threadIdx.x == 0) {
        int len = 0;
        bool is_start = (t == 0) || (o_enc[n] != 0);
        if (is_start) {
            int tt = t + 1;
            while (tt < TT && o_enc[b * TT + tt] == 0) ++tt;
            len = tt - t;
        }
        s_len = len;
    }
    __syncthreads();
    const float mu = g_stats[0], rs = g_stats[1];
    const int len = s_len;
    for (int e = threadIdx.x; e < EMBc; e += 256) {
        size_t bi = (size_t)n * EMBc + e;
        float v = (g_emb[bi] - mu) * rs;
        float o = v + r_enc[bi];
        if (len) {
            float sum = 0.f;
            for (int s = 0; s < len; ++s)
                sum += g_emb[(size_t)(n + s) * EMBc + e];
            o += (sum / (float)len - mu) * rs;
        }
        out[bi] = o;
    }
}

// ---------------- launcher --------------------------------------------------
extern "C" void kernel_launch(void* const* d_in, const int* in_sizes, int n_in,
                              void* d_out, int out_size)
{
    const float* x     = (const float*)d_in[0];
    const int*   o_enc = (const int*)  d_in[1];
    const float* r_enc = (const float*)d_in[2];
    const float* Wq    = (const float*)d_in[3];
    const float* bq    = (const float*)d_in[4];
    const float* Wk    = (const float*)d_in[5];
    const float* bk    = (const float*)d_in[6];
    const float* Wv    = (const float*)d_in[7];
    const float* bv    = (const float*)d_in[8];
    const float* Er    = (const float*)d_in[9];
    const float* W1    = (const float*)d_in[10];
    const float* b1    = (const float*)d_in[11];
    const float* W2    = (const float*)d_in[12];
    const float* b2    = (const float*)d_in[13];
    const float* We    = (const float*)d_in[14];
    const float* be    = (const float*)d_in[15];
    float* out = (float*)d_out;

    cudaFuncSetAttribute(qkv_kernel, cudaFuncAttributeMaxDynamicSharedMemorySize,
                         QKV_SMEM * 4);
    cudaFuncSetAttribute(attn_kernel, cudaFuncAttributeMaxDynamicSharedMemorySize,
                         ATT_SMEM * 4);
    cudaFuncSetAttribute(ffn_kernel, cudaFuncAttributeMaxDynamicSharedMemorySize,
                         FFN_SMEM * 4);

    qkv_kernel<<<dim3(NTOK / 2, 3), 512, QKV_SMEM * 4>>>(x, Wq, bq, Wk, bk, Wv, bv);

    attn_kernel<<<NTOK, 256, ATT_SMEM * 4>>>(Er);

    ffn_kernel<<<NTOK / 2, 512, FFN_SMEM * 4>>>(W1, b1, W2, b2);

    dim3 g2(EMBc / 128, NTOK / 128);   // (4, 32) = 128 blocks
    we_gemm_kernel<<<g2, 512>>>(We, be);

    stats_kernel<<<1, 32>>>();

    final_kernel<<<NTOK, 256>>>(o_enc, r_enc, out);
}

// round 6
// speedup vs baseline: 1.4362x; 1.1003x over previous
#include <cuda_runtime.h>
#include <math.h>

#define NTOK 4096          // B*T
#define TT   1024
#define Fc   6144          // SW*FB = 96*64
#define EMBc 512

typedef unsigned long long u64;

// ---------------- packed f32x2 helpers (FFMA2 path) -------------------------
__device__ __forceinline__ void fma2(u64 &d, u64 a, u64 b) {
    asm("fma.rn.f32x2 %0, %1, %2, %0;" : "+l"(d) : "l"(a), "l"(b));
}
__device__ __forceinline__ u64 dup2(float x) {
    u64 r; asm("mov.b64 %0, {%1, %1};" : "=l"(r) : "f"(x)); return r;
}
__device__ __forceinline__ float2 up2(u64 v) {
    float2 p; asm("mov.b64 {%0, %1}, %2;" : "=f"(p.x), "=f"(p.y) : "l"(v)); return p;
}
__device__ __forceinline__ float hsum2(u64 v) { float2 p = up2(v); return p.x + p.y; }

// ---------------- scratch ---------------------------------------------------
__device__ float  g_q[(size_t)NTOK * Fc];     // [(n,l), d]
__device__ float  g_kT[(size_t)NTOK * Fc];    // [n][d][m]
__device__ float  g_vT[(size_t)NTOK * Fc];    // [n][d][m]
__device__ float  g_attT[(size_t)NTOK * Fc];  // [n][d][l]
__device__ float  g_mid[(size_t)NTOK * Fc];   // (B,T,F)
__device__ float  g_emb[(size_t)NTOK * EMBc];
__device__ double g_part[512];                // 256 blocks * 2
__device__ float  g_stats[2];

// ---------------- kernel 1: batched QKV GEMM --------------------------------
#define QKV_SMEM (12416 + 9216)

__global__ __launch_bounds__(512, 2) void qkv_kernel(
    const float* __restrict__ x,
    const float* __restrict__ Wq, const float* __restrict__ bq,
    const float* __restrict__ Wk, const float* __restrict__ bk,
    const float* __restrict__ Wv, const float* __restrict__ bv)
{
    extern __shared__ float sm[];
    float* As = sm;
    float* Ws = sm + 12416;

    const int tid = threadIdx.x;
    const int mat = blockIdx.y;
    const int n0  = blockIdx.x * 2;
    const size_t xbase = (size_t)n0 * Fc;

    const float* W  = (mat == 0) ? Wq : (mat == 1) ? Wk : Wv;
    const float* bi = (mat == 0) ? bq : (mat == 1) ? bk : bv;

    for (int idx = tid; idx < 12288; idx += 512) {
        int d = idx >> 7, m = idx & 127;
        As[idx] = x[xbase + (size_t)(m >> 6) * Fc + d * 64 + (m & 63)];
    }
    for (int idx = tid; idx < 9216; idx += 512) Ws[idx] = W[idx];
    __syncthreads();

    const int r0 = (tid >> 5) * 8;
    const int lane = tid & 31;
    u64 acc[4][3];
    #pragma unroll
    for (int i = 0; i < 4; ++i)
        #pragma unroll
        for (int j = 0; j < 3; ++j) acc[i][j] = 0;

    #pragma unroll 2
    for (int d = 0; d < 96; ++d) {
        ulonglong2 a01 = *(const ulonglong2*)&As[d * 128 + r0];
        ulonglong2 a23 = *(const ulonglong2*)&As[d * 128 + r0 + 4];
        u64 ap[4] = {a01.x, a01.y, a23.x, a23.y};
        u64 w0 = dup2(Ws[d * 96 + lane]);
        u64 w1 = dup2(Ws[d * 96 + lane + 32]);
        u64 w2 = dup2(Ws[d * 96 + lane + 64]);
        #pragma unroll
        for (int i = 0; i < 4; ++i) {
            fma2(acc[i][0], ap[i], w0);
            fma2(acc[i][1], ap[i], w1);
            fma2(acc[i][2], ap[i], w2);
        }
    }
    float bb[3] = {bi[lane], bi[lane + 32], bi[lane + 64]};

    if (mat == 0) {
        #pragma unroll
        for (int i = 0; i < 4; ++i)
            #pragma unroll
            for (int j = 0; j < 3; ++j) {
                float2 p = up2(acc[i][j]);
                int row = r0 + 2 * i, col = lane + 32 * j;
                g_q[xbase + (size_t)row * 96 + col]       = p.x + bb[j];
                g_q[xbase + (size_t)(row + 1) * 96 + col] = p.y + bb[j];
            }
    } else {
        __syncthreads();
        #pragma unroll
        for (int i = 0; i < 4; ++i)
            #pragma unroll
            for (int j = 0; j < 3; ++j) {
                float2 p = up2(acc[i][j]);
                int col = lane + 32 * j, row = r0 + 2 * i;
                As[col * 129 + row]     = p.x + bb[j];
                As[col * 129 + row + 1] = p.y + bb[j];
            }
        __syncthreads();
        float* gout = (mat == 1) ? g_kT : g_vT;
        for (int idx = tid; idx < 12288; idx += 512) {
            int d = idx >> 7, m = idx & 127;
            gout[xbase + (size_t)(m >> 6) * Fc + d * 64 + (m & 63)] = As[d * 129 + m];
        }
    }
}

// ---------------- kernel 2: per-token attention -----------------------------
#define ATT_SMEM 28800

__global__ __launch_bounds__(256, 2) void attn_kernel(const float* __restrict__ Er)
{
    extern __shared__ float sm[];
    float* sQ  = sm;             // [l*97 + d]
    float* sKT = sm + 6208;      // [d*64 + m]
    float* sVT = sKT + 6144;     // [d*64 + m]
    float* sEr = sVT + 6144;     // [d*66 + j]
    float* sS  = sEr + 2112;     // [l*64 + m]
    float* sR  = sS + 4096;      // [l*64 + j]

    const int tid = threadIdx.x;
    const int n   = blockIdx.x;
    const size_t base = (size_t)n * Fc;

    for (int idx = tid; idx < Fc; idx += 256) {
        int l = idx / 96, d = idx - l * 96;
        sQ[l * 97 + d] = g_q[base + idx];
    }
    for (int idx = tid; idx < Fc; idx += 256) sKT[idx] = g_kT[base + idx];
    for (int idx = tid; idx < Fc; idx += 256) sVT[idx] = g_vT[base + idx];
    for (int idx = tid; idx < 2048; idx += 256) {
        int j = idx >> 5, d = idx & 31;
        sEr[d * 66 + j] = Er[idx];
    }
    __syncthreads();

    const float scale = 0.17677669529663687f;
    const int wid = tid >> 5, lane = tid & 31;
    const int l0 = (tid >> 4) * 4, m0 = (tid & 15) * 4;
    const int d0 = (tid & 15) * 2;

    for (int h = 0; h < 3; ++h) {
        const int hb = h * 32;
        u64 aS[4][2], aR[4][2];
        #pragma unroll
        for (int r = 0; r < 4; ++r) { aS[r][0]=0; aS[r][1]=0; aR[r][0]=0; aR[r][1]=0; }
        #pragma unroll 2
        for (int d = 0; d < 32; ++d) {
            u64 k0 = *(const u64*)&sKT[(hb + d) * 64 + m0];
            u64 k1 = *(const u64*)&sKT[(hb + d) * 64 + m0 + 2];
            u64 e0 = *(const u64*)&sEr[d * 66 + m0];
            u64 e1 = *(const u64*)&sEr[d * 66 + m0 + 2];
            #pragma unroll
            for (int r = 0; r < 4; ++r) {
                u64 q = dup2(sQ[(l0 + r) * 97 + hb + d]);
                fma2(aS[r][0], q, k0); fma2(aS[r][1], q, k1);
                fma2(aR[r][0], q, e0); fma2(aR[r][1], q, e1);
            }
        }
        #pragma unroll
        for (int r = 0; r < 4; ++r) {
            *(u64*)&sS[(l0 + r) * 64 + m0]     = aS[r][0];
            *(u64*)&sS[(l0 + r) * 64 + m0 + 2] = aS[r][1];
            *(u64*)&sR[(l0 + r) * 64 + m0]     = aR[r][0];
            *(u64*)&sR[(l0 + r) * 64 + m0 + 2] = aR[r][1];
        }
        __syncthreads();

        for (int l = wid; l < 64; l += 8) {
            int m1 = lane + 32;
            int j0 = min(lane + 63 - l, 63);
            int j1 = min(m1 + 63 - l, 63);
            float v0 = (lane <= l) ? (sS[l * 64 + lane] + sR[l * 64 + j0]) * scale : -1e30f;
            float v1 = (m1   <= l) ? (sS[l * 64 + m1]   + sR[l * 64 + j1]) * scale : -1e30f;
            float mx = fmaxf(v0, v1);
            #pragma unroll
            for (int o = 16; o; o >>= 1) mx = fmaxf(mx, __shfl_xor_sync(0xffffffffu, mx, o));
            float e0 = __expf(v0 - mx), e1 = __expf(v1 - mx);
            float ssum = e0 + e1;
            #pragma unroll
            for (int o = 16; o; o >>= 1) ssum += __shfl_xor_sync(0xffffffffu, ssum, o);
            float inv = 1.0f / ssum;
            sS[l * 64 + lane] = e0 * inv;
            sS[l * 64 + m1]   = e1 * inv;
        }
        __syncthreads();

        u64 po[4][2];
        #pragma unroll
        for (int r = 0; r < 4; ++r) { po[r][0] = 0; po[r][1] = 0; }
        #pragma unroll 2
        for (int mp = 0; mp < 32; ++mp) {
            u64 v0 = *(const u64*)&sVT[(hb + d0) * 64 + 2 * mp];
            u64 v1 = *(const u64*)&sVT[(hb + d0 + 1) * 64 + 2 * mp];
            #pragma unroll
            for (int r = 0; r < 4; ++r) {
                u64 pv = *(const u64*)&sS[(l0 + r) * 64 + 2 * mp];
                fma2(po[r][0], pv, v0);
                fma2(po[r][1], pv, v1);
            }
        }
        __syncthreads();
        #pragma unroll
        for (int r = 0; r < 4; ++r) {
            sQ[(l0 + r) * 97 + hb + d0]     = hsum2(po[r][0]);
            sQ[(l0 + r) * 97 + hb + d0 + 1] = hsum2(po[r][1]);
        }
    }
    __syncthreads();
    for (int idx = tid; idx < Fc; idx += 256) {
        int d = idx >> 6, l = idx & 63;
        g_attT[base + idx] = sQ[l * 97 + d];
    }
}

// ---------------- kernel 3: fused FFN, 64-col hidden chunks, 2 CTAs/SM ------
// smem: sX 12672 | sW 6144 | sH 64*132=8448  = 27264 floats (109 KB)
#define FFN_SMEM (12672 + 6144 + 8448)

__global__ __launch_bounds__(512, 2) void ffn_kernel(
    const float* __restrict__ W1, const float* __restrict__ b1,
    const float* __restrict__ W2, const float* __restrict__ b2)
{
    extern __shared__ float sm[];
    float* sX = sm;            // att tile [d*132 + m]; reused as out bounce
    float* sW = sm + 12672;    // W1 chunk [d*64+c] / W2 chunk [k*96+c]
    float* sH = sW + 6144;     // h chunk [c*132 + m], c in [0,64)

    const int tid = threadIdx.x;
    const int n0  = blockIdx.x * 2;
    const size_t base = (size_t)n0 * Fc;

    for (int idx = tid; idx < 12288; idx += 512) {
        int d = idx >> 7, m = idx & 127;
        sX[d * 132 + m] = g_attT[base + (size_t)(m >> 6) * Fc + d * 64 + (m & 63)];
    }

    const int r0 = (tid >> 5) * 8;
    const int lane = tid & 31;
    u64 acc2[4][3];
    #pragma unroll
    for (int i = 0; i < 4; ++i)
        #pragma unroll
        for (int j = 0; j < 3; ++j) acc2[i][j] = 0;

    for (int ch = 0; ch < 6; ++ch) {
        __syncthreads();
        for (int idx = tid; idx < 6144; idx += 512) {        // W1 chunk 96x64
            int d = idx >> 6, c = idx & 63;
            sW[idx] = W1[d * 384 + ch * 64 + c];
        }
        __syncthreads();
        u64 ha[4][2];
        #pragma unroll
        for (int i = 0; i < 4; ++i) { ha[i][0] = 0; ha[i][1] = 0; }
        #pragma unroll 2
        for (int d = 0; d < 96; ++d) {
            ulonglong2 a01 = *(const ulonglong2*)&sX[d * 132 + r0];
            ulonglong2 a23 = *(const ulonglong2*)&sX[d * 132 + r0 + 4];
            u64 ap[4] = {a01.x, a01.y, a23.x, a23.y};
            u64 w0 = dup2(sW[d * 64 + lane]);
            u64 w1 = dup2(sW[d * 64 + lane + 32]);
            #pragma unroll
            for (int i = 0; i < 4; ++i) {
                fma2(ha[i][0], ap[i], w0);
                fma2(ha[i][1], ap[i], w1);
            }
        }
        float bb1[2] = {b1[ch * 64 + lane], b1[ch * 64 + lane + 32]};
        #pragma unroll
        for (int i = 0; i < 4; ++i)
            #pragma unroll
            for (int j = 0; j < 2; ++j) {
                float2 p = up2(ha[i][j]);
                int c = lane + 32 * j, row = r0 + 2 * i;
                sH[c * 132 + row]     = fmaxf(p.x + bb1[j], 0.f);
                sH[c * 132 + row + 1] = fmaxf(p.y + bb1[j], 0.f);
            }
        __syncthreads();
        for (int idx = tid; idx < 6144; idx += 512) {        // W2 chunk 64x96
            int k = idx / 96, c = idx - k * 96;
            sW[idx] = W2[(ch * 64 + k) * 96 + c];
        }
        __syncthreads();
        #pragma unroll 2
        for (int k = 0; k < 64; ++k) {
            ulonglong2 a01 = *(const ulonglong2*)&sH[k * 132 + r0];
            ulonglong2 a23 = *(const ulonglong2*)&sH[k * 132 + r0 + 4];
            u64 ap[4] = {a01.x, a01.y, a23.x, a23.y};
            u64 w0 = dup2(sW[k * 96 + lane]);
            u64 w1 = dup2(sW[k * 96 + lane + 32]);
            u64 w2 = dup2(sW[k * 96 + lane + 64]);
            #pragma unroll
            for (int i = 0; i < 4; ++i) {
                fma2(acc2[i][0], ap[i], w0);
                fma2(acc2[i][1], ap[i], w1);
                fma2(acc2[i][2], ap[i], w2);
            }
        }
    }
    // epilogue: bounce-transpose via sX (dead) then coalesced store
    __syncthreads();
    float bb2[3] = {b2[lane], b2[lane + 32], b2[lane + 64]};
    #pragma unroll
    for (int i = 0; i < 4; ++i)
        #pragma unroll
        for (int j = 0; j < 3; ++j) {
            float2 p = up2(acc2[i][j]);
            int c = lane + 32 * j, row = r0 + 2 * i;
            sX[c * 132 + row]     = p.x + bb2[j];
            sX[c * 132 + row + 1] = p.y + bb2[j];
        }
    __syncthreads();
    for (int idx = tid; idx < 12288; idx += 512) {
        int c = idx >> 7, m = idx & 127;
        g_mid[base + (size_t)(m >> 6) * Fc + c * 64 + (m & 63)] = sX[c * 132 + m];
    }
}

// ---------------- kernel 4: We GEMM 64x128x32 tiles, 4 CTAs/SM --------------
#define WBK 32

__global__ __launch_bounds__(256, 4) void we_gemm_kernel(
    const float* __restrict__ We, const float* __restrict__ be)
{
    __shared__ __align__(16) float As[WBK * 68];    // [k*68 + m], padded
    __shared__ __align__(16) float Bs[WBK * 128];   // [k*128 + c]
    __shared__ double red[16];

    const int tid = threadIdx.x;
    const int e0 = blockIdx.x * 128;
    const int n0 = blockIdx.y * 64;
    const int r0 = (tid >> 5) * 8;      // 8 warps x 8 rows = 64
    const int c0 = (tid & 31) * 4;      // lane x 4 cols = 128

    u64 acc[4][4];
    #pragma unroll
    for (int i = 0; i < 4; ++i)
        #pragma unroll
        for (int j = 0; j < 4; ++j) acc[i][j] = 0;

    for (int k0 = 0; k0 < Fc; k0 += WBK) {
        __syncthreads();
        #pragma unroll
        for (int q = 0; q < 2; ++q) {                 // A: 64 rows x 32 k
            int lin = tid + q * 256;
            int m = lin >> 3, kq = (lin & 7) * 4;
            float4 v = *(const float4*)&g_mid[(size_t)(n0 + m) * Fc + k0 + kq];
            As[(kq + 0) * 68 + m] = v.x;
            As[(kq + 1) * 68 + m] = v.y;
            As[(kq + 2) * 68 + m] = v.z;
            As[(kq + 3) * 68 + m] = v.w;
        }
        #pragma unroll
        for (int q = 0; q < 4; ++q) {                 // B: 32 k x 128 c
            int lin = tid + q * 256;
            int k = lin >> 5, c4 = (lin & 31) * 4;
            *(float4*)&Bs[k * 128 + c4] =
                *(const float4*)&We[(size_t)(k0 + k) * EMBc + e0 + c4];
        }
        __syncthreads();
        #pragma unroll
        for (int k = 0; k < WBK; ++k) {
            ulonglong2 a01 = *(const ulonglong2*)&As[k * 68 + r0];
            ulonglong2 a23 = *(const ulonglong2*)&As[k * 68 + r0 + 4];
            u64 ap[4] = {a01.x, a01.y, a23.x, a23.y};
            float4 bv = *(const float4*)&Bs[k * 128 + c0];
            u64 bd[4] = {dup2(bv.x), dup2(bv.y), dup2(bv.z), dup2(bv.w)};
            #pragma unroll
            for (int i = 0; i < 4; ++i)
                #pragma unroll
                for (int j = 0; j < 4; ++j) fma2(acc[i][j], ap[i], bd[j]);
        }
    }

    float beb[4];
    #pragma unroll
    for (int j = 0; j < 4; ++j) beb[j] = be[e0 + c0 + j];

    double s = 0.0, s2 = 0.0;
    #pragma unroll
    for (int i = 0; i < 4; ++i) {
        float4 o0, o1;
        float2 p0 = up2(acc[i][0]), p1 = up2(acc[i][1]);
        float2 p2 = up2(acc[i][2]), p3 = up2(acc[i][3]);
        o0.x = p0.x + beb[0]; o0.y = p1.x + beb[1]; o0.z = p2.x + beb[2]; o0.w = p3.x + beb[3];
        o1.x = p0.y + beb[0]; o1.y = p1.y + beb[1]; o1.z = p2.y + beb[2]; o1.w = p3.y + beb[3];
        int row0 = n0 + r0 + 2 * i;
        *(float4*)&g_emb[(size_t)row0 * EMBc + e0 + c0]       = o0;
        *(float4*)&g_emb[(size_t)(row0 + 1) * EMBc + e0 + c0] = o1;
        s  += (double)o0.x + o0.y + o0.z + o0.w + (double)o1.x + o1.y + o1.z + o1.w;
        s2 += (double)o0.x * o0.x + (double)o0.y * o0.y + (double)o0.z * o0.z + (double)o0.w * o0.w
            + (double)o1.x * o1.x + (double)o1.y * o1.y + (double)o1.z * o1.z + (double)o1.w * o1.w;
    }
    #pragma unroll
    for (int o = 16; o; o >>= 1) {
        s  += __shfl_xor_sync(0xffffffffu, s, o);
        s2 += __shfl_xor_sync(0xffffffffu, s2, o);
    }
    const int wrp = tid >> 5, lane = tid & 31;
    if (lane == 0) { red[wrp] = s; red[wrp + 8] = s2; }
    __syncthreads();
    if (tid == 0) {
        double ts = 0.0, ts2 = 0.0;
        #pragma unroll
        for (int i = 0; i < 8; ++i) { ts += red[i]; ts2 += red[i + 8]; }
        int bid = blockIdx.y * gridDim.x + blockIdx.x;   // < 256
        g_part[bid * 2]     = ts;
        g_part[bid * 2 + 1] = ts2;
    }
}

// ---------------- kernel 5: finalize mean / rstd ----------------------------
__global__ void stats_kernel()
{
    if (threadIdx.x == 0) {
        double s = 0.0, s2 = 0.0;
        for (int i = 0; i < 256; ++i) { s += g_part[2 * i]; s2 += g_part[2 * i + 1]; }
        double cnt = (double)NTOK * (double)EMBc;
        double mu  = s / cnt;
        double var = s2 / cnt - mu * mu;
        g_stats[0] = (float)mu;
        g_stats[1] = (float)(1.0 / sqrt(var + 1e-8));
    }
}

// ---------------- kernel 6: normalize + segment means + residual ------------
__global__ __launch_bounds__(256) void final_kernel(
    const int* __restrict__ o_enc, const float* __restrict__ r_enc,
    float* __restrict__ out)
{
    const int n = blockIdx.x;
    const int b = n >> 10, t = n & 1023;
    __shared__ int s_len;
    if (threadIdx.x == 0) {
        int len = 0;
        bool is_start = (t == 0) || (o_enc[n] != 0);
        if (is_start) {
            int tt = t + 1;
            while (tt < TT && o_enc[b * TT + tt] == 0) ++tt;
            len = tt - t;
        }
        s_len = len;
    }
    __syncthreads();
    const float mu = g_stats[0], rs = g_stats[1];
    const int len = s_len;
    for (int e = threadIdx.x; e < EMBc; e += 256) {
        size_t bi = (size_t)n * EMBc + e;
        float v = (g_emb[bi] - mu) * rs;
        float o = v + r_enc[bi];
        if (len) {
            float sum = 0.f;
            for (int s = 0; s < len; ++s)
                sum += g_emb[(size_t)(n + s) * EMBc + e];
            o += (sum / (float)len - mu) * rs;
        }
        out[bi] = o;
    }
}

// ---------------- launcher --------------------------------------------------
extern "C" void kernel_launch(void* const* d_in, const int* in_sizes, int n_in,
                              void* d_out, int out_size)
{
    const float* x     = (const float*)d_in[0];
    const int*   o_enc = (const int*)  d_in[1];
    const float* r_enc = (const float*)d_in[2];
    const float* Wq    = (const float*)d_in[3];
    const float* bq    = (const float*)d_in[4];
    const float* Wk    = (const float*)d_in[5];
    const float* bk    = (const float*)d_in[6];
    const float* Wv    = (const float*)d_in[7];
    const float* bv    = (const float*)d_in[8];
    const float* Er    = (const float*)d_in[9];
    const float* W1    = (const float*)d_in[10];
    const float* b1    = (const float*)d_in[11];
    const float* W2    = (const float*)d_in[12];
    const float* b2    = (const float*)d_in[13];
    const float* We    = (const float*)d_in[14];
    const float* be    = (const float*)d_in[15];
    float* out = (float*)d_out;

    cudaFuncSetAttribute(qkv_kernel, cudaFuncAttributeMaxDynamicSharedMemorySize,
                         QKV_SMEM * 4);
    cudaFuncSetAttribute(attn_kernel, cudaFuncAttributeMaxDynamicSharedMemorySize,
                         ATT_SMEM * 4);
    cudaFuncSetAttribute(ffn_kernel, cudaFuncAttributeMaxDynamicSharedMemorySize,
                         FFN_SMEM * 4);

    qkv_kernel<<<dim3(NTOK / 2, 3), 512, QKV_SMEM * 4>>>(x, Wq, bq, Wk, bk, Wv, bv);

    attn_kernel<<<NTOK, 256, ATT_SMEM * 4>>>(Er);

    ffn_kernel<<<NTOK / 2, 512, FFN_SMEM * 4>>>(W1, b1, W2, b2);

    dim3 g2(EMBc / 128, NTOK / 64);    // (4, 64) = 256 blocks
    we_gemm_kernel<<<g2, 256>>>(We, be);

    stats_kernel<<<1, 32>>>();

    final_kernel<<<NTOK, 256>>>(o_enc, r_enc, out);
}